// round 1
// baseline (speedup 1.0000x reference)
#include <cuda_runtime.h>

#define NB 16384
#define NSTEPS 100
#define DTC 0.01f
#define SQDT 0.1f
#define SIG0 0.5f

// Shared-memory layout per MLP (float offsets)
#define OFF_A   0                      // W1 row 0 (t weights) [64]
#define OFF_C   64                     // W1 row 1 (y weights) [64]
#define OFF_B1  128                    // b1 [64]
#define OFF_B2  192                    // b2 [64]
#define OFF_W2T 256                    // W2^T [64 rows x stride 68]
#define W2T_STRIDE 68
#define OFF_W3  (OFF_W2T + 64*W2T_STRIDE)   // 4608: W3 padded [64][4]
#define OFF_B3  (OFF_W3 + 64*4)             // 4864: b3 padded [4]
#define MLP_FLOATS 4880                     // padded, 16B-aligned stride

__device__ float g_partials[256];

__global__ __launch_bounds__(128) void bsde_kernel(
    const float* __restrict__ y0, const float* __restrict__ Y0,
    const float* __restrict__ zW1, const float* __restrict__ zb1,
    const float* __restrict__ zW2, const float* __restrict__ zb2,
    const float* __restrict__ zW3, const float* __restrict__ zb3,
    const float* __restrict__ qW1, const float* __restrict__ qb1,
    const float* __restrict__ qW2, const float* __restrict__ qb2,
    const float* __restrict__ qW3, const float* __restrict__ qb3,
    const float* __restrict__ dW, const float* __restrict__ dZ)
{
    __shared__ float smw[2 * MLP_FLOATS];
    __shared__ float red[128];
    const int tx = threadIdx.x;

    // ---- Stage weights into shared memory (transpose W2, pad W3 to 4 cols) ----
    for (int idx = tx; idx < 4096; idx += 128) {
        int n = idx & 63, k = idx >> 6;          // zW2[k*64 + n]
        smw[OFF_W2T + n * W2T_STRIDE + k] = zW2[idx];
        smw[MLP_FLOATS + OFF_W2T + n * W2T_STRIDE + k] = qW2[idx];
    }
    if (tx < 64) {
        int n = tx;
        smw[OFF_A + n]  = zW1[n];
        smw[OFF_C + n]  = zW1[64 + n];
        smw[OFF_B1 + n] = zb1[n];
        smw[OFF_B2 + n] = zb2[n];
        smw[OFF_W3 + n * 4 + 0] = zW3[n * 3 + 0];
        smw[OFF_W3 + n * 4 + 1] = zW3[n * 3 + 1];
        smw[OFF_W3 + n * 4 + 2] = zW3[n * 3 + 2];
        smw[OFF_W3 + n * 4 + 3] = 0.f;
        smw[MLP_FLOATS + OFF_A + n]  = qW1[n];
        smw[MLP_FLOATS + OFF_C + n]  = qW1[64 + n];
        smw[MLP_FLOATS + OFF_B1 + n] = qb1[n];
        smw[MLP_FLOATS + OFF_B2 + n] = qb2[n];
        smw[MLP_FLOATS + OFF_W3 + n * 4 + 0] = qW3[n];
        smw[MLP_FLOATS + OFF_W3 + n * 4 + 1] = 0.f;
        smw[MLP_FLOATS + OFF_W3 + n * 4 + 2] = 0.f;
        smw[MLP_FLOATS + OFF_W3 + n * 4 + 3] = 0.f;
    }
    if (tx < 4) {
        smw[OFF_B3 + tx] = (tx < 3) ? zb3[tx] : 0.f;
        smw[MLP_FLOATS + OFF_B3 + tx] = (tx == 0) ? qb3[0] : 0.f;
    }
    __syncthreads();

    // ---- Path simulation: lane pair (h=0,1) cooperates on one path ----
    const int tid  = blockIdx.x * 128 + tx;
    const int path = tid >> 1;
    const int h    = tid & 1;

    float y    = y0[0];
    float Yv   = Y0[0];
    float t    = 0.f;
    float loss = 0.f;
    const float* dWp = dW + path * 3;
    const float* dZp = dZ + path * 3;

    float zdw = 0.f, zdz = 0.f, qv = 0.f;

    #pragma unroll 1
    for (int i = 0; i < NSTEPS; ++i) {
        // noise for this step (latency hidden behind ~9K cycles of MLP math)
        float dw0 = dWp[0] * SQDT, dw1 = dWp[1] * SQDT, dw2 = dWp[2] * SQDT;
        float dz0 = dZp[0] * SQDT, dz1 = dZp[1] * SQDT, dz2 = dZp[2] * SQDT;
        dWp += NB * 3; dZp += NB * 3;

        #pragma unroll 1
        for (int m = 0; m < 2; ++m) {           // m=0: z-MLP, m=1: q-MLP
            const float* Wm = smw + m * MLP_FLOATS;

            // layer 1: h1_n = relu(b1 + t*A + y*C), full 64 per thread
            float h1[64];
            #pragma unroll
            for (int n = 0; n < 64; n += 4) {
                float4 a = *(const float4*)(Wm + OFF_A + n);
                float4 c = *(const float4*)(Wm + OFF_C + n);
                float4 b = *(const float4*)(Wm + OFF_B1 + n);
                h1[n + 0] = fmaxf(fmaf(t, a.x, fmaf(y, c.x, b.x)), 0.f);
                h1[n + 1] = fmaxf(fmaf(t, a.y, fmaf(y, c.y, b.y)), 0.f);
                h1[n + 2] = fmaxf(fmaf(t, a.z, fmaf(y, c.z, b.z)), 0.f);
                h1[n + 3] = fmaxf(fmaf(t, a.w, fmaf(y, c.w, b.w)), 0.f);
            }

            // layer 2 (split: this thread owns neurons n = 16g + 2u + h),
            // layer 3 fused into each group's epilogue
            float o0 = 0.f, o1 = 0.f, o2 = 0.f;
            #pragma unroll 1
            for (int g = 0; g < 4; ++g) {
                const float* w2base = Wm + OFF_W2T + (g * 16 + h) * W2T_STRIDE;
                float acc[8];
                #pragma unroll
                for (int u = 0; u < 8; ++u)
                    acc[u] = Wm[OFF_B2 + g * 16 + 2 * u + h];
                #pragma unroll
                for (int k = 0; k < 64; k += 4) {
                    #pragma unroll
                    for (int u = 0; u < 8; ++u) {
                        float4 w = *(const float4*)(w2base + 2 * u * W2T_STRIDE + k);
                        acc[u] = fmaf(h1[k + 0], w.x, acc[u]);
                        acc[u] = fmaf(h1[k + 1], w.y, acc[u]);
                        acc[u] = fmaf(h1[k + 2], w.z, acc[u]);
                        acc[u] = fmaf(h1[k + 3], w.w, acc[u]);
                    }
                }
                const float* w3base = Wm + OFF_W3 + (g * 16 + h) * 4;
                #pragma unroll
                for (int u = 0; u < 8; ++u) {
                    float hv = fmaxf(acc[u], 0.f);
                    float4 w3 = *(const float4*)(w3base + 2 * u * 4);
                    o0 = fmaf(hv, w3.x, o0);
                    o1 = fmaf(hv, w3.y, o1);
                    o2 = fmaf(hv, w3.z, o2);
                }
            }

            // combine the pair's partial outputs, add bias
            o0 += __shfl_xor_sync(0xffffffffu, o0, 1);
            o1 += __shfl_xor_sync(0xffffffffu, o1, 1);
            o2 += __shfl_xor_sync(0xffffffffu, o2, 1);
            o0 += Wm[OFF_B3 + 0];
            o1 += Wm[OFF_B3 + 1];
            o2 += Wm[OFF_B3 + 2];

            if (m == 0) {
                zdw = o0 * dw0 + o1 * dw1 + o2 * dw2;
                zdz = o0 * dz0 + o1 * dz1 + o2 * dz2;
            } else {
                qv = o0;
            }
        }

        // SDE / BSDE update (residual = z.dw - z.dz; Y cancels)
        float f = 0.5f * qv * qv;
        y  = y + qv * DTC + SIG0 * (dw0 + dw1 + dw2);
        Yv = Yv - f * DTC + zdw;
        float r = zdw - zdz;
        loss = fmaf(r, r, loss);
        t += DTC;
    }
    float term = Yv - y * y;
    loss = fmaf(term, term, loss);   // both lanes of pair add the same value -> scale by 0.5 later

    // ---- deterministic block reduction ----
    red[tx] = loss;
    __syncthreads();
    #pragma unroll
    for (int s = 64; s > 0; s >>= 1) {
        if (tx < s) red[tx] += red[tx + s];
        __syncthreads();
    }
    if (tx == 0) g_partials[blockIdx.x] = red[0];
}

__global__ void bsde_reduce(float* __restrict__ out)
{
    __shared__ float red[256];
    int tx = threadIdx.x;
    red[tx] = g_partials[tx];
    __syncthreads();
    #pragma unroll
    for (int s = 128; s > 0; s >>= 1) {
        if (tx < s) red[tx] += red[tx + s];
        __syncthreads();
    }
    if (tx == 0) out[0] = red[0] * (0.5f / (float)NB);
}

extern "C" void kernel_launch(void* const* d_in, const int* in_sizes, int n_in,
                              void* d_out, int out_size)
{
    const float* y0  = (const float*)d_in[0];
    const float* Y0  = (const float*)d_in[1];
    const float* zW1 = (const float*)d_in[2];
    const float* zb1 = (const float*)d_in[3];
    const float* zW2 = (const float*)d_in[4];
    const float* zb2 = (const float*)d_in[5];
    const float* zW3 = (const float*)d_in[6];
    const float* zb3 = (const float*)d_in[7];
    const float* qW1 = (const float*)d_in[8];
    const float* qb1 = (const float*)d_in[9];
    const float* qW2 = (const float*)d_in[10];
    const float* qb2 = (const float*)d_in[11];
    const float* qW3 = (const float*)d_in[12];
    const float* qb3 = (const float*)d_in[13];
    const float* dW  = (const float*)d_in[14];
    const float* dZ  = (const float*)d_in[15];

    bsde_kernel<<<256, 128>>>(y0, Y0, zW1, zb1, zW2, zb2, zW3, zb3,
                              qW1, qb1, qW2, qb2, qW3, qb3, dW, dZ);
    bsde_reduce<<<1, 256>>>((float*)d_out);
}

// round 2
// speedup vs baseline: 1.0555x; 1.0555x over previous
#include <cuda_runtime.h>

#define NB 16384
#define NSTEPS 100
#define DTC 0.01f
#define SQDT 0.1f
#define SIG0 0.5f

typedef unsigned long long u64;

// packed f32x2 helpers (FFMA2 — only reachable via PTX, SASS_QUICKREF §patterns)
#define FMA2(d, a, b, c) \
    asm("fma.rn.f32x2 %0, %1, %2, %3;" : "=l"(d) : "l"(a), "l"(b), "l"(c))
#define PACK2(d, lo, hi) \
    asm("mov.b64 %0, {%1, %2};" : "=l"(d) : "r"(lo), "r"(hi))
#define UNPACK2(lo, hi, d) \
    asm("mov.b64 {%0, %1}, %2;" : "=r"(lo), "=r"(hi) : "l"(d))

// Shared-memory layout per MLP (float offsets)
#define OFF_A    0            // W1 row 0 (t weights) [64]
#define OFF_C    64           // W1 row 1 (y weights) [64]
#define OFF_B1   128          // b1 [64]
#define OFF_B2   192          // b2 [64]
#define OFF_W2   256          // two halves: [h][k=0..63][32 floats]
#define W2_HALF  2052         // 64*32 + 4 pad floats (bank-shift between halves)
#define OFF_W3T  (OFF_W2 + 2 * W2_HALF)   // 4360: W3 transposed [3][64]
#define OFF_B3   (OFF_W3T + 192)          // 4552
#define MLP_FLOATS 4560                   // 18240 B, 16B-aligned stride

__device__ float g_partials[128];

__global__ __launch_bounds__(256) void bsde_kernel(
    const float* __restrict__ y0, const float* __restrict__ Y0,
    const float* __restrict__ zW1, const float* __restrict__ zb1,
    const float* __restrict__ zW2, const float* __restrict__ zb2,
    const float* __restrict__ zW3, const float* __restrict__ zb3,
    const float* __restrict__ qW1, const float* __restrict__ qb1,
    const float* __restrict__ qW2, const float* __restrict__ qb2,
    const float* __restrict__ qW3, const float* __restrict__ qb3,
    const float* __restrict__ dW, const float* __restrict__ dZ)
{
    __shared__ float smw[2 * MLP_FLOATS];
    __shared__ float red[256];
    const int tx = threadIdx.x;

    // ---- Stage weights: W2 split into lane-halves, W3 transposed ----
    for (int idx = tx; idx < 4096; idx += 256) {
        int k = idx >> 6, n = idx & 63;
        int hh = n >> 5, j = n & 31;
        smw[OFF_W2 + hh * W2_HALF + k * 32 + j] = zW2[idx];
        smw[MLP_FLOATS + OFF_W2 + hh * W2_HALF + k * 32 + j] = qW2[idx];
    }
    if (tx < 64) {
        int n = tx;
        smw[OFF_A + n]  = zW1[n];
        smw[OFF_C + n]  = zW1[64 + n];
        smw[OFF_B1 + n] = zb1[n];
        smw[OFF_B2 + n] = zb2[n];
        smw[OFF_W3T + 0 * 64 + n] = zW3[n * 3 + 0];
        smw[OFF_W3T + 1 * 64 + n] = zW3[n * 3 + 1];
        smw[OFF_W3T + 2 * 64 + n] = zW3[n * 3 + 2];
        smw[MLP_FLOATS + OFF_A + n]  = qW1[n];
        smw[MLP_FLOATS + OFF_C + n]  = qW1[64 + n];
        smw[MLP_FLOATS + OFF_B1 + n] = qb1[n];
        smw[MLP_FLOATS + OFF_B2 + n] = qb2[n];
        smw[MLP_FLOATS + OFF_W3T + 0 * 64 + n] = qW3[n];
        smw[MLP_FLOATS + OFF_W3T + 1 * 64 + n] = 0.f;
        smw[MLP_FLOATS + OFF_W3T + 2 * 64 + n] = 0.f;
    }
    if (tx < 4) {
        smw[OFF_B3 + tx] = (tx < 3) ? zb3[tx] : 0.f;
        smw[MLP_FLOATS + OFF_B3 + tx] = (tx == 0) ? qb3[0] : 0.f;
    }
    __syncthreads();

    // ---- Path simulation: lane pair (h=0,1); thread owns neurons [h*32, h*32+32) ----
    const int tid  = blockIdx.x * 256 + tx;
    const int path = tid >> 1;
    const int h    = tid & 1;

    float y    = y0[0];
    float Yv   = Y0[0];
    float t    = 0.f;
    float loss = 0.f;
    const float* dWp = dW + path * 3;
    const float* dZp = dZ + path * 3;

    float zdw = 0.f, zdz = 0.f, qv = 0.f;

    #pragma unroll 1
    for (int i = 0; i < NSTEPS; ++i) {
        float dw0 = dWp[0] * SQDT, dw1 = dWp[1] * SQDT, dw2 = dWp[2] * SQDT;
        float dz0 = dZp[0] * SQDT, dz1 = dZp[1] * SQDT, dz2 = dZp[2] * SQDT;
        dWp += NB * 3; dZp += NB * 3;

        u64 t2, y2;
        {
            unsigned int tb = __float_as_uint(t), yb = __float_as_uint(y);
            PACK2(t2, tb, tb);
            PACK2(y2, yb, yb);
        }

        #pragma unroll 1
        for (int m = 0; m < 2; ++m) {          // m=0: z-MLP, m=1: q-MLP
            const float* Wm = smw + m * MLP_FLOATS;

            // ---- layer 1 (packed): h1_n = relu(b1 + t*A + y*C) ----
            float h1[64];
            #pragma unroll
            for (int n = 0; n < 64; n += 2) {
                u64 a2  = *(const u64*)(Wm + OFF_A + n);
                u64 c2  = *(const u64*)(Wm + OFF_C + n);
                u64 b2v = *(const u64*)(Wm + OFF_B1 + n);
                u64 r;
                FMA2(r, y2, c2, b2v);
                FMA2(r, t2, a2, r);
                unsigned int lo, hi;
                UNPACK2(lo, hi, r);
                h1[n]     = fmaxf(__uint_as_float(lo), 0.f);
                h1[n + 1] = fmaxf(__uint_as_float(hi), 0.f);
            }

            // ---- layer 2 (packed neuron pairs): 16 f32x2 accumulators ----
            const float* w2  = Wm + OFF_W2 + h * W2_HALF;
            const float* b2p = Wm + OFF_B2 + h * 32;
            u64 acc[16];
            #pragma unroll
            for (int u = 0; u < 16; ++u)
                acc[u] = *(const u64*)(b2p + 2 * u);

            #pragma unroll
            for (int k = 0; k < 64; ++k) {
                u64 hk;
                unsigned int hb = __float_as_uint(h1[k]);
                PACK2(hk, hb, hb);
                const ulonglong2* wk = (const ulonglong2*)(w2 + k * 32);
                #pragma unroll
                for (int j = 0; j < 8; ++j) {
                    ulonglong2 w = wk[j];
                    FMA2(acc[2 * j],     hk, w.x, acc[2 * j]);
                    FMA2(acc[2 * j + 1], hk, w.y, acc[2 * j + 1]);
                }
            }

            // ---- layer 3 (packed, W3 transposed) ----
            const float* w3c0 = Wm + OFF_W3T + 0 * 64 + h * 32;
            const float* w3c1 = Wm + OFF_W3T + 1 * 64 + h * 32;
            const float* w3c2 = Wm + OFF_W3T + 2 * 64 + h * 32;
            u64 o0p = 0ull, o1p = 0ull, o2p = 0ull;
            #pragma unroll
            for (int u = 0; u < 16; ++u) {
                unsigned int lo, hi;
                UNPACK2(lo, hi, acc[u]);
                float f0 = fmaxf(__uint_as_float(lo), 0.f);
                float f1 = fmaxf(__uint_as_float(hi), 0.f);
                u64 hp;
                PACK2(hp, __float_as_uint(f0), __float_as_uint(f1));
                FMA2(o0p, hp, *(const u64*)(w3c0 + 2 * u), o0p);
                FMA2(o1p, hp, *(const u64*)(w3c1 + 2 * u), o1p);
                FMA2(o2p, hp, *(const u64*)(w3c2 + 2 * u), o2p);
            }
            unsigned int l0, h0, l1, hh1, l2, h2;
            UNPACK2(l0, h0, o0p);
            UNPACK2(l1, hh1, o1p);
            UNPACK2(l2, h2, o2p);
            float o0 = __uint_as_float(l0) + __uint_as_float(h0);
            float o1 = __uint_as_float(l1) + __uint_as_float(hh1);
            float o2 = __uint_as_float(l2) + __uint_as_float(h2);

            // combine the pair's halves, add bias
            o0 += __shfl_xor_sync(0xffffffffu, o0, 1);
            o1 += __shfl_xor_sync(0xffffffffu, o1, 1);
            o2 += __shfl_xor_sync(0xffffffffu, o2, 1);
            o0 += Wm[OFF_B3 + 0];
            o1 += Wm[OFF_B3 + 1];
            o2 += Wm[OFF_B3 + 2];

            if (m == 0) {
                zdw = o0 * dw0 + o1 * dw1 + o2 * dw2;
                zdz = o0 * dz0 + o1 * dz1 + o2 * dz2;
            } else {
                qv = o0;
            }
        }

        // SDE / BSDE update (residual = z.dw - z.dz; Y cancels)
        float f = 0.5f * qv * qv;
        y  = y + qv * DTC + SIG0 * (dw0 + dw1 + dw2);
        Yv = Yv - f * DTC + zdw;
        float r = zdw - zdz;
        loss = fmaf(r, r, loss);
        t += DTC;
    }
    float term = Yv - y * y;
    loss = fmaf(term, term, loss);   // duplicated across lane pair -> scaled by 0.5 below

    // ---- deterministic block reduction ----
    red[tx] = loss;
    __syncthreads();
    #pragma unroll
    for (int s = 128; s > 0; s >>= 1) {
        if (tx < s) red[tx] += red[tx + s];
        __syncthreads();
    }
    if (tx == 0) g_partials[blockIdx.x] = red[0];
}

__global__ void bsde_reduce(float* __restrict__ out)
{
    __shared__ float red[128];
    int tx = threadIdx.x;
    red[tx] = g_partials[tx];
    __syncthreads();
    #pragma unroll
    for (int s = 64; s > 0; s >>= 1) {
        if (tx < s) red[tx] += red[tx + s];
        __syncthreads();
    }
    if (tx == 0) out[0] = red[0] * (0.5f / (float)NB);
}

extern "C" void kernel_launch(void* const* d_in, const int* in_sizes, int n_in,
                              void* d_out, int out_size)
{
    const float* y0  = (const float*)d_in[0];
    const float* Y0  = (const float*)d_in[1];
    const float* zW1 = (const float*)d_in[2];
    const float* zb1 = (const float*)d_in[3];
    const float* zW2 = (const float*)d_in[4];
    const float* zb2 = (const float*)d_in[5];
    const float* zW3 = (const float*)d_in[6];
    const float* zb3 = (const float*)d_in[7];
    const float* qW1 = (const float*)d_in[8];
    const float* qb1 = (const float*)d_in[9];
    const float* qW2 = (const float*)d_in[10];
    const float* qb2 = (const float*)d_in[11];
    const float* qW3 = (const float*)d_in[12];
    const float* qb3 = (const float*)d_in[13];
    const float* dW  = (const float*)d_in[14];
    const float* dZ  = (const float*)d_in[15];

    bsde_kernel<<<128, 256>>>(y0, Y0, zW1, zb1, zW2, zb2, zW3, zb3,
                              qW1, qb1, qW2, qb2, qW3, qb3, dW, dZ);
    bsde_reduce<<<1, 128>>>((float*)d_out);
}